// round 1
// baseline (speedup 1.0000x reference)
#include <cuda_runtime.h>
#include <math.h>

#define NB   32
#define HH   128
#define WW   128
#define CC   80
#define CHN  84
#define KTOP 100
#define NBINS 32768
#define CAP  262144
#define SORTN 2048

__device__ unsigned int g_count[NB];
__device__ unsigned int g_hist[NB][NBINS];
__device__ unsigned long long g_cand[NB][CAP];

__global__ void clear_kernel() {
    int i = blockIdx.x * blockDim.x + threadIdx.x;
    if (i < NB * NBINS) ((unsigned int*)g_hist)[i] = 0u;
    if (i < NB) g_count[i] = 0u;
}

// Fused: sigmoid-monotone 3x3 max-pool peak detection in RAW space + candidate
// append (key = order-mapped raw bits) + histogram for later threshold select.
__global__ void __launch_bounds__(320, 1) peak_kernel(const float* __restrict__ det) {
    __shared__ __align__(16) float buf[3][34][80];
    const int b   = blockIdx.y;
    const int x0  = blockIdx.x * 32;
    const int tid = threadIdx.x;
    const int c   = tid % 80;      // channel owned by this thread
    const int g   = tid / 80;      // x-group 0..3
    const int xbase = g * 8;       // 8 output x per thread

    const float NEGINF = __int_as_float(0xff800000);

    auto load_row = [&](int gy, int s) {
        if (gy >= 0 && gy < HH) {
            const float4* rp = reinterpret_cast<const float4*>(
                det + ((size_t)b * HH + gy) * (size_t)WW * CHN);
            for (int i = tid; i < 680; i += 320) {       // 34 x * 20 float4
                int xl = i / 20, q = i - xl * 20;
                int gx = x0 - 1 + xl;
                float4 v;
                if (gx >= 0 && gx < WW) v = rp[gx * 21 + q];
                else v = make_float4(NEGINF, NEGINF, NEGINF, NEGINF);
                *reinterpret_cast<float4*>(&buf[s][xl][q * 4]) = v;
            }
        } else {
            float4 v = make_float4(NEGINF, NEGINF, NEGINF, NEGINF);
            for (int i = tid; i < 680; i += 320) {
                int xl = i / 20, q = i - xl * 20;
                *reinterpret_cast<float4*>(&buf[s][xl][q * 4]) = v;
            }
        }
    };

    load_row(-1, 2);
    load_row(0, 0);

    for (int y = 0; y < HH; y++) {
        load_row(y + 1, (y + 1) % 3);
        __syncthreads();
        const int s0 = (y + 2) % 3, s1 = y % 3, s2 = (y + 1) % 3;

        auto vmax3 = [&](int t, float& ctrv) {
            float a0 = buf[s0][t][c];
            float a1 = buf[s1][t][c];
            float a2 = buf[s2][t][c];
            ctrv = a1;
            return fmaxf(a0, fmaxf(a1, a2));
        };

        float junk, ctrC, ctrN;
        float vmL = vmax3(xbase, junk);          // smem x = lx-1+1 for lx=xbase
        float vmC = vmax3(xbase + 1, ctrC);
        #pragma unroll
        for (int k = 0; k < 8; k++) {
            int lx = xbase + k;
            float vmN = vmax3(lx + 2, ctrN);
            float m   = fmaxf(vmL, fmaxf(vmC, vmN));
            float ctr = ctrC;
            float d   = m - ctr;                 // >= 0

            bool cand;
            if (d < 3.6e-4f) {
                cand = true;                     // diff <= d/4 < 9e-5 : certain peak
            } else if (d > 0.042f && fmaxf(fabsf(ctr), fabsf(m)) < 6.0f) {
                cand = false;                    // diff >= d*sigma'(6) > 1.03e-4
            } else {                             // uncertain band: exact f32 test
                float s  = 1.0f / (1.0f + expf(-ctr));
                float sm = 1.0f / (1.0f + expf(-m));
                cand = fabsf(s - sm) < 1e-4f;
            }

            unsigned mask = __ballot_sync(0xFFFFFFFFu, cand);
            if (cand) {
                unsigned bits   = __float_as_uint(m);
                unsigned mapped = (bits & 0x80000000u) ? ~bits : (bits | 0x80000000u);
                atomicAdd(&g_hist[b][mapped >> 17], 1u);

                int lane = tid & 31;
                int leader = __ffs(mask) - 1;
                unsigned base;
                if (lane == leader) base = atomicAdd(&g_count[b], (unsigned)__popc(mask));
                base = __shfl_sync(mask, base, leader);
                unsigned pos = base + __popc(mask & ((1u << lane) - 1u));

                unsigned idx = ((unsigned)y * WW + (unsigned)(x0 + lx)) * CC + (unsigned)c;
                if (pos < CAP)
                    g_cand[b][pos] = ((unsigned long long)mapped << 21)
                                   | (unsigned long long)(0x1FFFFFu - idx);
            }
            vmL = vmC; vmC = vmN; ctrC = ctrN;
        }
        __syncthreads();
    }
}

// Per-batch: histogram suffix-scan -> raw threshold (1-bin margin) -> exact
// sigmoid on ~130 finalists -> bitonic sort (value desc, index asc) -> decode.
__global__ void __launch_bounds__(1024) topk_kernel(const float* __restrict__ det,
                                                    float* __restrict__ out) {
    const int b   = blockIdx.x;
    const int tid = threadIdx.x;
    __shared__ unsigned sA[1024], sB[1024];
    __shared__ unsigned long long sel[SORTN];
    __shared__ int s_cc;
    __shared__ unsigned s_above, s_T;
    __shared__ int s_n;

    unsigned csum = 0;
    #pragma unroll
    for (int k = 0; k < 32; k++) csum += g_hist[b][tid * 32 + k];
    sA[tid] = csum;
    if (tid == 0) { s_cc = -1; s_above = 0u; s_n = 0; }
    __syncthreads();

    // inclusive suffix sum over 1024 chunk sums (ping-pong Hillis-Steele)
    unsigned *src = sA, *dst = sB;
    for (int dstep = 1; dstep < 1024; dstep <<= 1) {
        unsigned v = src[tid];
        if (tid + dstep < 1024) v += src[tid + dstep];
        dst[tid] = v;
        __syncthreads();
        unsigned* t = src; src = dst; dst = t;
    }

    if (src[tid] >= (unsigned)KTOP && (tid == 1023 || src[tid + 1] < (unsigned)KTOP)) {
        s_cc = tid;
        s_above = (tid == 1023) ? 0u : src[tid + 1];
    }
    __syncthreads();
    if (tid == 0) {
        unsigned T = 0;
        if (s_cc >= 0) {
            unsigned acc = s_above;
            for (int bin = s_cc * 32 + 31; bin >= s_cc * 32; bin--) {
                acc += g_hist[b][bin];
                if (acc >= (unsigned)KTOP) { T = (unsigned)bin; break; }
            }
        }
        if (T > 0) T -= 1;          // one-bin margin: sigmoid collision safety
        s_T = T;
    }
    __syncthreads();

    const unsigned thr = s_T << 17;
    unsigned cnt = g_count[b]; if (cnt > CAP) cnt = CAP;
    for (unsigned i = tid; i < cnt; i += 1024) {
        unsigned long long key = g_cand[b][i];
        unsigned mapped = (unsigned)(key >> 21);
        if (mapped >= thr) {
            unsigned bits = (mapped & 0x80000000u) ? (mapped ^ 0x80000000u) : ~mapped;
            float raw = __uint_as_float(bits);
            float sg  = 1.0f / (1.0f + expf(-raw));   // exact f32 value for ordering
            int p = atomicAdd(&s_n, 1);
            if (p < SORTN)
                sel[p] = ((unsigned long long)__float_as_uint(sg) << 21)
                       | (key & 0x1FFFFFull);
        }
    }
    __syncthreads();
    int n = s_n; if (n > SORTN) n = SORTN;
    for (int i = tid; i < SORTN; i += 1024) if (i >= n) sel[i] = 0ull;

    for (unsigned ksz = 2; ksz <= (unsigned)SORTN; ksz <<= 1)
        for (unsigned j = ksz >> 1; j > 0; j >>= 1) {
            __syncthreads();
            for (unsigned i = tid; i < (unsigned)SORTN; i += 1024) {
                unsigned ixj = i ^ j;
                if (ixj > i) {
                    unsigned long long a = sel[i], q = sel[ixj];
                    bool desc = ((i & ksz) == 0);
                    if (desc ? (a < q) : (a > q)) { sel[i] = q; sel[ixj] = a; }
                }
            }
        }
    __syncthreads();

    if (tid < KTOP) {
        unsigned long long key = sel[tid];
        float score = 0.0f; unsigned idx = 0u;
        if (tid < n) {
            score = __uint_as_float((unsigned)(key >> 21));
            idx   = 0x1FFFFFu - (unsigned)(key & 0x1FFFFFull);
        }
        unsigned cl = idx % CC;
        unsigned sp = idx / CC;
        unsigned xs = sp % WW;
        unsigned ys = sp / WW;
        const float* wh = det + (((size_t)b * HH + ys) * WW + xs) * CHN + CC;
        float w0 = wh[0], w1 = wh[1], w2 = wh[2], w3 = wh[3];
        float fy = (float)ys, fx = (float)xs;
        float* o = out + ((size_t)b * KTOP + tid) * 6;
        o[0] = (fy - w0) * 0.0078125f;   // /128
        o[1] = (fx - w1) * 0.0078125f;
        o[2] = (fy + w2) * 0.0078125f;
        o[3] = (fx + w3) * 0.0078125f;
        o[4] = (float)cl;
        o[5] = score;
    }
}

extern "C" void kernel_launch(void* const* d_in, const int* in_sizes, int n_in,
                              void* d_out, int out_size) {
    const float* det = (const float*)d_in[0];
    float* out = (float*)d_out;
    (void)in_sizes; (void)n_in; (void)out_size;

    clear_kernel<<<(NB * NBINS + 255) / 256, 256>>>();
    dim3 g1(WW / 32, NB);
    peak_kernel<<<g1, 320>>>(det);
    topk_kernel<<<NB, 1024>>>(det, out);
}

// round 2
// speedup vs baseline: 3.2859x; 3.2859x over previous
#include <cuda_runtime.h>
#include <math.h>

#define NB    32
#define HH    128
#define WW    128
#define CC    80
#define CHN   84
#define KTOP  100
#define NBINS 32768
#define CAP   262144
#define SORTN 2048

#define XT    32
#define YT    16
#define THR   320
#define ROWF4 680      /* 34 x * 20 float4 */
#define RING  5
#define ROWCAP 1024

__device__ unsigned int g_count[NB];
__device__ unsigned int g_hist[NB][NBINS];
__device__ unsigned long long g_cand[NB][CAP];

__global__ void clear_kernel() {
    unsigned i = blockIdx.x * blockDim.x + threadIdx.x;
    const unsigned n4 = NB * NBINS / 4;
    uint4 z = make_uint4(0u, 0u, 0u, 0u);
    for (unsigned j = i; j < n4; j += gridDim.x * blockDim.x)
        ((uint4*)g_hist)[j] = z;
    if (i < NB) g_count[i] = 0u;
}

__device__ __forceinline__ unsigned su32(const void* p) {
    return (unsigned)__cvta_generic_to_shared(p);
}

// Fused sigmoid-monotone 3x3 peak detect (raw space) with cp.async row
// pipeline + shared-memory candidate staging (no ATOMG on the compute path).
__global__ void __launch_bounds__(THR, 3) peak_kernel(const float* __restrict__ det) {
    extern __shared__ __align__(16) float smem[];
    float* ringbuf = smem;                                   // RING*34*80 floats
    unsigned long long* sbuf = (unsigned long long*)(smem + RING * 34 * 80);
    unsigned* s_cnt  = (unsigned*)(sbuf + ROWCAP);           // [2] parity counters
    unsigned* s_base = s_cnt + 2;

    const int b   = blockIdx.z;
    const int x0  = blockIdx.x * XT;
    const int y0  = blockIdx.y * YT;
    const int tid = threadIdx.x;
    const int c   = tid % 80;
    const int g   = tid / 80;
    const int xbase = g * 8;

    if (tid < 2) s_cnt[tid] = 0u;

    auto issue_row = [&](int ry) {
        int gy = y0 - 1 + ry;
        gy = max(0, min(HH - 1, gy));
        const float* rp = det + ((size_t)(b * HH + gy) * WW) * CHN;
        float* slot = ringbuf + (ry % RING) * (34 * 80);
        #pragma unroll
        for (int t = 0; t < 3; t++) {
            int i = tid + t * THR;
            if (i < ROWF4) {
                int xl = i / 20, q = i - xl * 20;
                int gx = x0 - 1 + xl;
                gx = max(0, min(WW - 1, gx));     // clamp == SAME-pad for max
                const float* gp = rp + gx * CHN + q * 4;
                unsigned sa = su32(slot + xl * 80 + q * 4);
                asm volatile("cp.async.cg.shared.global [%0], [%1], 16;"
                             :: "r"(sa), "l"(gp));
            }
        }
    };

    issue_row(0); asm volatile("cp.async.commit_group;");
    issue_row(1); asm volatile("cp.async.commit_group;");
    issue_row(2); asm volatile("cp.async.commit_group;");

    for (int y = 0; y < YT; y++) {
        int ry = y + 3;
        if (ry <= YT + 1) issue_row(ry);
        asm volatile("cp.async.commit_group;");
        asm volatile("cp.async.wait_group 1;");   // rows <= y+2 resident
        __syncthreads();

        const float* r0 = ringbuf + ( y      % RING) * (34 * 80);
        const float* r1 = ringbuf + ((y + 1) % RING) * (34 * 80);
        const float* r2 = ringbuf + ((y + 2) % RING) * (34 * 80);
        const int p  = y & 1;
        const int gy = y0 + y;

        auto vmax3 = [&](int t, float& ctr) {
            float a0 = r0[t * 80 + c];
            float a1 = r1[t * 80 + c];
            float a2 = r2[t * 80 + c];
            ctr = a1;
            return fmaxf(a0, fmaxf(a1, a2));
        };

        float junk, ctrC, ctrN;
        float vmL = vmax3(xbase, junk);
        float vmC = vmax3(xbase + 1, ctrC);
        #pragma unroll
        for (int k = 0; k < 8; k++) {
            float vmN = vmax3(xbase + k + 2, ctrN);
            float m   = fmaxf(vmL, fmaxf(vmC, vmN));
            float ctr = ctrC;
            float d   = m - ctr;

            bool cand;
            if (d < 3.6e-4f) {
                cand = true;                       // diff <= d/4 < 1e-4 (covers d=0)
            } else if (d > 0.042f && fmaxf(fabsf(ctr), fabsf(m)) < 6.0f) {
                cand = false;                      // diff >= d*sigma'(6) > 1e-4
            } else {
                float s  = 1.0f / (1.0f + expf(-ctr));
                float sm = 1.0f / (1.0f + expf(-m));
                cand = fabsf(s - sm) < 1e-4f;
            }

            unsigned mask = __ballot_sync(0xFFFFFFFFu, cand);
            if (cand) {
                unsigned bits   = __float_as_uint(m);
                unsigned mapped = (bits & 0x80000000u) ? ~bits : (bits | 0x80000000u);
                int lane = tid & 31, leader = __ffs(mask) - 1;
                unsigned base;
                if (lane == leader) base = atomicAdd(&s_cnt[p], (unsigned)__popc(mask));
                base = __shfl_sync(mask, base, leader);
                unsigned pos = base + __popc(mask & ((1u << lane) - 1u));
                unsigned idx = ((unsigned)gy * WW + (unsigned)(x0 + xbase + k)) * CC
                             + (unsigned)c;
                unsigned long long key = ((unsigned long long)mapped << 21)
                                       | (unsigned long long)(0x1FFFFFu - idx);
                if (pos < ROWCAP) {
                    sbuf[pos] = key;
                } else {                            // overflow fallback (rare)
                    unsigned gp2 = atomicAdd(&g_count[b], 1u);
                    if (gp2 < CAP) g_cand[b][gp2] = key;
                    atomicAdd(&g_hist[b][mapped >> 17], 1u);
                }
            }
            vmL = vmC; vmC = vmN; ctrC = ctrN;
        }
        __syncthreads();

        unsigned cnt = min(s_cnt[p], (unsigned)ROWCAP);
        if (tid == 0) {
            s_base[0] = atomicAdd(&g_count[b], cnt);   // ONE ATOMG per block-row
            s_cnt[p ^ 1] = 0u;                         // reset for next row
        }
        __syncthreads();
        unsigned gbase = s_base[0];
        for (unsigned i = tid; i < cnt; i += THR) {
            unsigned long long key = sbuf[i];
            unsigned mapped = (unsigned)(key >> 21);
            atomicAdd(&g_hist[b][mapped >> 17], 1u);   // fire-and-forget RED
            unsigned pos = gbase + i;
            if (pos < CAP) g_cand[b][pos] = key;
        }
        // next iteration's post-wait __syncthreads covers flush/buffer reuse
    }
}

// Per-batch: histogram suffix-scan -> raw threshold (1-bin margin) -> exact
// sigmoid on finalists -> bitonic sort (value desc, index asc) -> decode.
__global__ void __launch_bounds__(1024) topk_kernel(const float* __restrict__ det,
                                                    float* __restrict__ out) {
    const int b   = blockIdx.x;
    const int tid = threadIdx.x;
    __shared__ unsigned sA[1024], sB[1024];
    __shared__ unsigned long long sel[SORTN];
    __shared__ int s_cc;
    __shared__ unsigned s_above, s_T;
    __shared__ int s_n;

    unsigned csum = 0;
    #pragma unroll
    for (int k = 0; k < 32; k++) csum += g_hist[b][tid * 32 + k];
    sA[tid] = csum;
    if (tid == 0) { s_cc = -1; s_above = 0u; s_n = 0; }
    __syncthreads();

    unsigned *src = sA, *dst = sB;
    for (int dstep = 1; dstep < 1024; dstep <<= 1) {
        unsigned v = src[tid];
        if (tid + dstep < 1024) v += src[tid + dstep];
        dst[tid] = v;
        __syncthreads();
        unsigned* t = src; src = dst; dst = t;
    }

    if (src[tid] >= (unsigned)KTOP && (tid == 1023 || src[tid + 1] < (unsigned)KTOP)) {
        s_cc = tid;
        s_above = (tid == 1023) ? 0u : src[tid + 1];
    }
    __syncthreads();
    if (tid == 0) {
        unsigned T = 0;
        if (s_cc >= 0) {
            unsigned acc = s_above;
            for (int bin = s_cc * 32 + 31; bin >= s_cc * 32; bin--) {
                acc += g_hist[b][bin];
                if (acc >= (unsigned)KTOP) { T = (unsigned)bin; break; }
            }
        }
        if (T > 0) T -= 1;              // one-bin margin for sigmoid collisions
        s_T = T;
    }
    __syncthreads();

    const unsigned thr = s_T << 17;
    unsigned cnt = g_count[b]; if (cnt > CAP) cnt = CAP;
    for (unsigned i0 = tid; i0 < cnt; i0 += 4096) {
        #pragma unroll
        for (int u = 0; u < 4; u++) {
            unsigned i = i0 + (unsigned)u * 1024u;
            if (i < cnt) {
                unsigned long long key = g_cand[b][i];
                unsigned mapped = (unsigned)(key >> 21);
                if (mapped >= thr) {
                    unsigned bits = (mapped & 0x80000000u) ? (mapped ^ 0x80000000u)
                                                           : ~mapped;
                    float raw = __uint_as_float(bits);
                    float sg  = 1.0f / (1.0f + expf(-raw));
                    int p = atomicAdd(&s_n, 1);
                    if (p < SORTN)
                        sel[p] = ((unsigned long long)__float_as_uint(sg) << 21)
                               | (key & 0x1FFFFFull);
                }
            }
        }
    }
    __syncthreads();
    int n = s_n; if (n > SORTN) n = SORTN;
    for (int i = tid; i < SORTN; i += 1024) if (i >= n) sel[i] = 0ull;

    for (unsigned ksz = 2; ksz <= (unsigned)SORTN; ksz <<= 1)
        for (unsigned j = ksz >> 1; j > 0; j >>= 1) {
            __syncthreads();
            for (unsigned i = tid; i < (unsigned)SORTN; i += 1024) {
                unsigned ixj = i ^ j;
                if (ixj > i) {
                    unsigned long long a = sel[i], q = sel[ixj];
                    bool desc = ((i & ksz) == 0);
                    if (desc ? (a < q) : (a > q)) { sel[i] = q; sel[ixj] = a; }
                }
            }
        }
    __syncthreads();

    if (tid < KTOP) {
        unsigned long long key = sel[tid];
        float score = 0.0f; unsigned idx = 0u;
        if (tid < n) {
            score = __uint_as_float((unsigned)(key >> 21));
            idx   = 0x1FFFFFu - (unsigned)(key & 0x1FFFFFull);
        }
        unsigned cl = idx % CC;
        unsigned sp = idx / CC;
        unsigned xs = sp % WW;
        unsigned ys = sp / WW;
        const float* wh = det + (((size_t)b * HH + ys) * WW + xs) * CHN + CC;
        float w0 = wh[0], w1 = wh[1], w2 = wh[2], w3 = wh[3];
        float fy = (float)ys, fx = (float)xs;
        float* o = out + ((size_t)b * KTOP + tid) * 6;
        o[0] = (fy - w0) * 0.0078125f;
        o[1] = (fx - w1) * 0.0078125f;
        o[2] = (fy + w2) * 0.0078125f;
        o[3] = (fx + w3) * 0.0078125f;
        o[4] = (float)cl;
        o[5] = score;
    }
}

extern "C" void kernel_launch(void* const* d_in, const int* in_sizes, int n_in,
                              void* d_out, int out_size) {
    const float* det = (const float*)d_in[0];
    float* out = (float*)d_out;
    (void)in_sizes; (void)n_in; (void)out_size;

    const int dynsmem = RING * 34 * 80 * 4 + ROWCAP * 8 + 16;
    cudaFuncSetAttribute(peak_kernel,
                         cudaFuncAttributeMaxDynamicSharedMemorySize, dynsmem);

    clear_kernel<<<512, 256>>>();
    dim3 g1(WW / XT, HH / YT, NB);
    peak_kernel<<<g1, THR, dynsmem>>>(det);
    topk_kernel<<<NB, 1024>>>(det, out);
}